// round 15
// baseline (speedup 1.0000x reference)
#include <cuda_runtime.h>
#include <math.h>

#define K 4
#define N 4096
#define D 256
#define S 32
#define MAXDEG 512
#define ETA 0.5f
#define COEFF 0.03125f   // S/(N*EPS^2)

// ---------------- scratch ----------------
__device__ float g_Zt[K * N * S];        // [k][n][s]
__device__ float g_MZt[K * N * S];       // [k][n][s]
__device__ float g_Minv[K * S * S];
__device__ float g_O[(size_t)N * (K * S)];   // O_cat: [n][k*S+s]
__device__ float g_O2[(size_t)N * (K * S)];  // (I - lam*L) @ O_cat
__device__ float g_Wc[K * S * D];        // w_k * U[k]^T : [k*S+s][d]
__device__ float g_gramP[K * 32 * S * S];
__device__ int   g_col[(size_t)N * MAXDEG];
__device__ int   g_deg[N];
__device__ float g_partials[N];
__device__ float g_orth[10];
__device__ int   g_ctr;       // zero-init; self-resetting
__device__ int   g_ctrK[K];   // zero-init; self-resetting

__device__ __forceinline__ float warpSum(float v) {
    v += __shfl_xor_sync(0xffffffffu, v, 16);
    v += __shfl_xor_sync(0xffffffffu, v, 8);
    v += __shfl_xor_sync(0xffffffffu, v, 4);
    v += __shfl_xor_sync(0xffffffffu, v, 2);
    v += __shfl_xor_sync(0xffffffffu, v, 1);
    return v;
}

// ================= mega kernel 1: Z (0..255) | CSR (256..767) | Wc (768..799) | orth (800..809) =================
__global__ void __launch_bounds__(256) k_mega1(const float* __restrict__ hops,
                                               const float* __restrict__ adj,
                                               const float* __restrict__ U,
                                               const float* __restrict__ hw) {
    __shared__ float sm[6528];
    int bx = blockIdx.x;
    int tid = threadIdx.x;

    if (bx < 256) {
        // ---------- Z = hops[k] @ U[k] : 64n x 32s tile, double-buffered ----------
        int k = bx >> 6;
        int n0 = (bx & 63) * 64;
        float* hsT0 = sm;            // 32*66
        float* hsT1 = sm + 2112;
        float* us0  = sm + 4224;     // 32*36
        float* us1  = sm + 5376;
        int ny = tid >> 3;
        int sx = (tid & 7) * 4;
        int rowq = tid >> 3;
        int q = tid & 7;
        const float* Hb = hops + ((size_t)k * N + n0) * D;
        const float* Ub = U + (size_t)k * D * S;

        float4 h0, h1, u0;
        h0 = *(const float4*)&Hb[(size_t)rowq * D + q * 4];
        h1 = *(const float4*)&Hb[(size_t)(rowq + 32) * D + q * 4];
        u0 = *(const float4*)&Ub[(size_t)rowq * S + q * 4];
        {
            float* hb = hsT0;
            hb[(q * 4 + 0) * 66 + rowq] = h0.x;
            hb[(q * 4 + 1) * 66 + rowq] = h0.y;
            hb[(q * 4 + 2) * 66 + rowq] = h0.z;
            hb[(q * 4 + 3) * 66 + rowq] = h0.w;
            hb[(q * 4 + 0) * 66 + rowq + 32] = h1.x;
            hb[(q * 4 + 1) * 66 + rowq + 32] = h1.y;
            hb[(q * 4 + 2) * 66 + rowq + 32] = h1.z;
            hb[(q * 4 + 3) * 66 + rowq + 32] = h1.w;
            *(float4*)&us0[rowq * 36 + q * 4] = u0;
        }
        __syncthreads();

        float a0x = 0.f, a0y = 0.f, a0z = 0.f, a0w = 0.f;
        float a1x = 0.f, a1y = 0.f, a1z = 0.f, a1w = 0.f;

        for (int ch = 0; ch < 8; ch++) {
            const float* hb = (ch & 1) ? hsT1 : hsT0;
            const float* ub = (ch & 1) ? us1 : us0;
            if (ch < 7) {
                int dc = (ch + 1) * 32;
                h0 = *(const float4*)&Hb[(size_t)rowq * D + dc + q * 4];
                h1 = *(const float4*)&Hb[(size_t)(rowq + 32) * D + dc + q * 4];
                u0 = *(const float4*)&Ub[(size_t)(dc + rowq) * S + q * 4];
            }
#pragma unroll
            for (int d = 0; d < 32; d++) {
                float2 h = *(const float2*)&hb[d * 66 + ny * 2];
                float4 u = *(const float4*)&ub[d * 36 + sx];
                a0x += h.x * u.x; a0y += h.x * u.y; a0z += h.x * u.z; a0w += h.x * u.w;
                a1x += h.y * u.x; a1y += h.y * u.y; a1z += h.y * u.z; a1w += h.y * u.w;
            }
            if (ch < 7) {
                float* hb2 = (ch & 1) ? hsT0 : hsT1;
                float* ub2 = (ch & 1) ? us0 : us1;
                hb2[(q * 4 + 0) * 66 + rowq] = h0.x;
                hb2[(q * 4 + 1) * 66 + rowq] = h0.y;
                hb2[(q * 4 + 2) * 66 + rowq] = h0.z;
                hb2[(q * 4 + 3) * 66 + rowq] = h0.w;
                hb2[(q * 4 + 0) * 66 + rowq + 32] = h1.x;
                hb2[(q * 4 + 1) * 66 + rowq + 32] = h1.y;
                hb2[(q * 4 + 2) * 66 + rowq + 32] = h1.z;
                hb2[(q * 4 + 3) * 66 + rowq + 32] = h1.w;
                *(float4*)&ub2[rowq * 36 + q * 4] = u0;
            }
            __syncthreads();
        }
        size_t base = ((size_t)k * N + n0 + ny * 2) * S + sx;
        *(float4*)&g_Zt[base] = make_float4(a0x, a0y, a0z, a0w);
        *(float4*)&g_Zt[base + S] = make_float4(a1x, a1y, a1z, a1w);
    } else if (bx < 768) {
        // ---------- CSR build (warp per row, float4 + 4 ballots per 128 cols) ----------
        int n = (bx - 256) * 8 + (tid >> 5);
        int lane = tid & 31;
        const float4* row = (const float4*)(adj + (size_t)n * N);
        int* dst = g_col + (size_t)n * MAXDEG;
        unsigned lm = (1u << lane) - 1u;
        int cnt = 0;
        for (int base = 0; base < N / 4; base += 32) {
            float4 a = row[base + lane];
            unsigned m0 = __ballot_sync(0xffffffffu, a.x != 0.0f);
            unsigned m1 = __ballot_sync(0xffffffffu, a.y != 0.0f);
            unsigned m2 = __ballot_sync(0xffffffffu, a.z != 0.0f);
            unsigned m3 = __ballot_sync(0xffffffffu, a.w != 0.0f);
            int pre = cnt + __popc(m0 & lm) + __popc(m1 & lm)
                          + __popc(m2 & lm) + __popc(m3 & lm);
            int j0 = (base + lane) * 4;
            if (a.x != 0.0f) dst[pre] = j0;
            int o1 = pre + ((m0 >> lane) & 1);
            if (a.y != 0.0f) dst[o1] = j0 + 1;
            int o2 = o1 + ((m1 >> lane) & 1);
            if (a.z != 0.0f) dst[o2] = j0 + 2;
            int o3 = o2 + ((m2 >> lane) & 1);
            if (a.w != 0.0f) dst[o3] = j0 + 3;
            cnt += __popc(m0) + __popc(m1) + __popc(m2) + __popc(m3);
        }
        if (lane == 0) g_deg[n] = min(cnt, MAXDEG);
    } else if (bx < 800) {
        // ---------- Wc[k*S+s][d] = w_k * U[k][d][s] ----------
        float m = fmaxf(fmaxf(hw[0], hw[1]), fmaxf(hw[2], hw[3]));
        float e0 = expf(hw[0] - m), e1 = expf(hw[1] - m);
        float e2 = expf(hw[2] - m), e3 = expf(hw[3] - m);
        float sum = e0 + e1 + e2 + e3;
        int base = ((bx - 768) * 256 + tid) * 4;
        float4 u4 = *(const float4*)&U[base];
        int k = base / (D * S);
        int rem = base % (D * S);
        int d = rem / S;
        int s = rem % S;
        float wk = (k == 0 ? e0 : k == 1 ? e1 : k == 2 ? e2 : e3) / sum;
        g_Wc[(k * S + s + 0) * D + d] = wk * u4.x;
        g_Wc[(k * S + s + 1) * D + d] = wk * u4.y;
        g_Wc[(k * S + s + 2) * D + d] = wk * u4.z;
        g_Wc[(k * S + s + 3) * D + d] = wk * u4.w;
    } else {
        // ---------- orth pair (s,t) dots; 4 t per thread ----------
        const int kk[10] = {0, 0, 0, 0, 1, 1, 1, 2, 2, 3};
        const int ll[10] = {0, 1, 2, 3, 1, 2, 3, 2, 3, 3};
        int p = bx - 800;
        int k = kk[p], l = ll[p];
        int s = tid >> 3;
        int t0 = (tid & 7) * 4;
        float* uk = sm;
        float* ul = sm + 2048;
        float* red = sm + 4096;
        float c0 = 0.f, c1 = 0.f, c2 = 0.f, c3 = 0.f;
        for (int dc = 0; dc < D; dc += 64) {
            for (int i = tid; i < 2048; i += 256) {
                uk[i] = U[((size_t)k * D + dc) * S + i];
                ul[i] = U[((size_t)l * D + dc) * S + i];
            }
            __syncthreads();
#pragma unroll 8
            for (int d = 0; d < 64; d++) {
                float a = uk[d * 32 + s];
                float4 b = *(const float4*)&ul[d * 32 + t0];
                c0 += a * b.x; c1 += a * b.y; c2 += a * b.z; c3 += a * b.w;
            }
            __syncthreads();
        }
        if (k == l) {
            if (s == t0 + 0) c0 -= 1.0f;
            if (s == t0 + 1) c1 -= 1.0f;
            if (s == t0 + 2) c2 -= 1.0f;
            if (s == t0 + 3) c3 -= 1.0f;
        }
        red[tid] = (c0 * c0 + c1 * c1) + (c2 * c2 + c3 * c3);
        __syncthreads();
        for (int off = 128; off > 0; off >>= 1) {
            if (tid < off) red[tid] += red[tid + off];
            __syncthreads();
        }
        if (tid == 0) g_orth[p] = red[0];
    }
}

// ================= gram partials + last-block-per-k inversion =================
__global__ void __launch_bounds__(1024) k_gram(void) {
    __shared__ float sm[4224];
    int tid = threadIdx.x;
    int k = blockIdx.x >> 5;
    int chunk = blockIdx.x & 31;
    float* zs = sm;
    const float4* Z4 = (const float4*)(g_Zt + ((size_t)k * N + chunk * 128) * S);
    ((float4*)zs)[tid] = Z4[tid];
    __syncthreads();
    int s = tid >> 5, t = tid & 31;
    float g0 = 0.f, g1 = 0.f, g2 = 0.f, g3 = 0.f;
#pragma unroll 8
    for (int n = 0; n < 128; n += 4) {
        g0 += zs[(n + 0) * 32 + s] * zs[(n + 0) * 32 + t];
        g1 += zs[(n + 1) * 32 + s] * zs[(n + 1) * 32 + t];
        g2 += zs[(n + 2) * 32 + s] * zs[(n + 2) * 32 + t];
        g3 += zs[(n + 3) * 32 + s] * zs[(n + 3) * 32 + t];
    }
    g_gramP[(((size_t)k * 32 + chunk) * S + s) * S + t] = (g0 + g1) + (g2 + g3);
    __threadfence();
    __shared__ int isLast;
    if (tid == 0) {
        int v = atomicAdd(&g_ctrK[k], 1);
        isLast = (v == 31);
        if (v == 31) atomicExch(&g_ctrK[k], 0);
    }
    __syncthreads();
    if (!isLast) return;
    __threadfence();
    float g = 0.f;
    for (int c = 0; c < 32; c++)
        g += g_gramP[(((size_t)k * 32 + c) * S + s) * S + t];
    float (*aug)[66] = (float(*)[66])sm;
    __syncthreads();
    aug[s][t] = (s == t ? 1.0f : 0.0f) + COEFF * g;
    aug[s][32 + t] = (s == t ? 1.0f : 0.0f);
    __syncthreads();
    int r0 = tid >> 6, c0 = tid & 63;
    int tid2 = tid + 1024;
    int r1 = tid2 >> 6, c1 = tid2 & 63;
    for (int p = 0; p < 32; p++) {
        float inv = 1.0f / aug[p][p];
        float f0 = aug[r0][p], pr0 = aug[p][c0];
        float f1 = aug[r1][p], pr1 = aug[p][c1];
        __syncthreads();
        if (r0 == p) aug[p][c0] = pr0 * inv;
        else         aug[r0][c0] -= f0 * inv * pr0;
        if (r1 == p) aug[p][c1] = pr1 * inv;
        else         aug[r1][c1] -= f1 * inv * pr1;
        __syncthreads();
    }
    g_Minv[k * S * S + s * S + t] = aug[s][32 + t];
}

// ================= MZt = Minv[k] @ Zt rows : conflict-free, 4 rows/warp =================
__global__ void k_MZ(void) {
    __shared__ float Msh[32 * 33];
    __shared__ float zsh[32 * 33];
    int k = blockIdx.y;
    int n0 = blockIdx.x * 32;
    int tid = threadIdx.x;
    int w = tid >> 5;
    int lane = tid & 31;
    {
        float4 v = ((const float4*)(g_Minv + k * S * S))[tid];
        int r = (tid * 4) >> 5;
        int c = (tid * 4) & 31;
        float* dst = &Msh[r * 33 + c];
        dst[0] = v.x; dst[1] = v.y; dst[2] = v.z; dst[3] = v.w;
    }
    {
        int r = tid >> 3, q = tid & 7;
        float4 v = *(const float4*)&g_Zt[((size_t)k * N + n0 + r) * S + q * 4];
        float* dst = &zsh[r * 33 + q * 4];
        dst[0] = v.x; dst[1] = v.y; dst[2] = v.z; dst[3] = v.w;
    }
    __syncthreads();
    float a0 = 0.f, a1 = 0.f, a2 = 0.f, a3 = 0.f;
    const float* z0 = &zsh[(w * 4 + 0) * 33];
    const float* z1 = &zsh[(w * 4 + 1) * 33];
    const float* z2 = &zsh[(w * 4 + 2) * 33];
    const float* z3 = &zsh[(w * 4 + 3) * 33];
#pragma unroll
    for (int t = 0; t < 32; t++) {
        float mv = Msh[t * 33 + lane];
        a0 += mv * z0[t];
        a1 += mv * z1[t];
        a2 += mv * z2[t];
        a3 += mv * z3[t];
    }
    size_t base = ((size_t)k * N + n0 + w * 4) * S + lane;
    g_MZt[base] = a0;
    g_MZt[base + S] = a1;
    g_MZt[base + 2 * S] = a2;
    g_MZt[base + 3 * S] = a3;
}

// ================= sparse attention: 2 warps per (k,n), interleaved halves =================
// Each warp processes 16-row chunks starting at half*16 with stride 32 (R13 body).
// Partial (l, acc) combined in smem: Σexp softmax is additive (no max tracking needed).
__global__ void __launch_bounds__(256) k_attn(void) {
    __shared__ float comb[4][33];    // 4 pairs per block: [f2*8..f2*8+7] acc, [32] l
    int w = threadIdx.x >> 5;
    int lane = threadIdx.x & 31;
    int gwarp = blockIdx.x * 8 + w;          // 0 .. 2*K*N-1
    int half = gwarp & 1;
    int pairId = gwarp >> 1;                 // (k,n)
    int k = pairId >> 12;
    int n = pairId & (N - 1);
    int pinb = w >> 1;                       // pair index within block 0..3
    const float* __restrict__ MZ = g_MZt + (size_t)k * N * S;
    const int* __restrict__ cols = g_col + (size_t)n * MAXDEG;
    int dn = g_deg[n];
    int f2 = lane & 3;
    int rr = lane >> 2;
    const float LOG2E = 1.4426950408889634f;
    const float* qp = &g_Zt[((size_t)k * N + n) * S + f2 * 8];
    float4 qa = *(const float4*)&qp[0];
    float4 qb = *(const float4*)&qp[4];
    qa.x *= LOG2E; qa.y *= LOG2E; qa.z *= LOG2E; qa.w *= LOG2E;
    qb.x *= LOG2E; qb.y *= LOG2E; qb.z *= LOG2E; qb.w *= LOG2E;

    float4 aa = make_float4(0.f, 0.f, 0.f, 0.f);
    float4 ab = make_float4(0.f, 0.f, 0.f, 0.f);
    float l = 0.f;

    int cstart = half * 16;
    // prologue: indices for first chunk of this half
    int j0 = (cstart + rr < dn) ? cols[cstart + rr] : 0;
    int j1 = (cstart + 8 + rr < dn) ? cols[cstart + 8 + rr] : 0;

    for (int c0 = cstart; c0 < dn; c0 += 32) {
        const float* vp0 = &MZ[(size_t)j0 * S + f2 * 8];
        const float* vp1 = &MZ[(size_t)j1 * S + f2 * 8];
        float4 va0 = *(const float4*)&vp0[0];
        float4 vb0 = *(const float4*)&vp0[4];
        float4 va1 = *(const float4*)&vp1[0];
        float4 vb1 = *(const float4*)&vp1[4];
        int nr0 = c0 + 32 + rr, nr1 = c0 + 40 + rr;
        int jn0 = (nr0 < dn) ? cols[nr0] : 0;
        int jn1 = (nr1 < dn) ? cols[nr1] : 0;

        bool in0 = (c0 + rr < dn);
        bool in1 = (c0 + 8 + rr < dn);

        float p0 = qa.x * va0.x + qa.y * va0.y + qa.z * va0.z + qa.w * va0.w
                 + qb.x * vb0.x + qb.y * vb0.y + qb.z * vb0.z + qb.w * vb0.w;
        float p1 = qa.x * va1.x + qa.y * va1.y + qa.z * va1.z + qa.w * va1.w
                 + qb.x * vb1.x + qb.y * vb1.y + qb.z * vb1.z + qb.w * vb1.w;
        p0 += __shfl_xor_sync(0xffffffffu, p0, 1);
        p1 += __shfl_xor_sync(0xffffffffu, p1, 1);
        p0 += __shfl_xor_sync(0xffffffffu, p0, 2);
        p1 += __shfl_xor_sync(0xffffffffu, p1, 2);
        p0 = in0 ? p0 : -1e30f;
        p1 = in1 ? p1 : -1e30f;
        float e0 = exp2f(p0);
        float e1 = exp2f(p1);
        l += e0 + e1;
        aa.x += e0 * va0.x; aa.y += e0 * va0.y; aa.z += e0 * va0.z; aa.w += e0 * va0.w;
        ab.x += e0 * vb0.x; ab.y += e0 * vb0.y; ab.z += e0 * vb0.z; ab.w += e0 * vb0.w;
        aa.x += e1 * va1.x; aa.y += e1 * va1.y; aa.z += e1 * va1.z; aa.w += e1 * va1.w;
        ab.x += e1 * vb1.x; ab.y += e1 * vb1.y; ab.z += e1 * vb1.z; ab.w += e1 * vb1.w;

        j0 = jn0; j1 = jn1;
    }

    // fold across the 8 rr-groups (xor 4, 8, 16)
#pragma unroll
    for (int off = 4; off <= 16; off <<= 1) {
        aa.x += __shfl_xor_sync(0xffffffffu, aa.x, off);
        aa.y += __shfl_xor_sync(0xffffffffu, aa.y, off);
        aa.z += __shfl_xor_sync(0xffffffffu, aa.z, off);
        aa.w += __shfl_xor_sync(0xffffffffu, aa.w, off);
        ab.x += __shfl_xor_sync(0xffffffffu, ab.x, off);
        ab.y += __shfl_xor_sync(0xffffffffu, ab.y, off);
        ab.z += __shfl_xor_sync(0xffffffffu, ab.z, off);
        ab.w += __shfl_xor_sync(0xffffffffu, ab.w, off);
        l    += __shfl_xor_sync(0xffffffffu, l, off);
    }

    // combine halves via smem
    if (half == 1 && rr == 0) {
        float* dst = &comb[pinb][f2 * 8];
        dst[0] = aa.x; dst[1] = aa.y; dst[2] = aa.z; dst[3] = aa.w;
        dst[4] = ab.x; dst[5] = ab.y; dst[6] = ab.z; dst[7] = ab.w;
        if (f2 == 0) comb[pinb][32] = l;
    }
    __syncthreads();
    if (half == 0 && rr == 0) {
        const float* src = &comb[pinb][f2 * 8];
        aa.x += src[0]; aa.y += src[1]; aa.z += src[2]; aa.w += src[3];
        ab.x += src[4]; ab.y += src[5]; ab.z += src[6]; ab.w += src[7];
        l += comb[pinb][32];
        float inv = 1.0f / l;
        float* dst = &g_O[(size_t)n * (K * S) + k * S + f2 * 8];
        *(float4*)&dst[0] = make_float4(aa.x * inv, aa.y * inv, aa.z * inv, aa.w * inv);
        *(float4*)&dst[4] = make_float4(ab.x * inv, ab.y * inv, ab.z * inv, ab.w * inv);
    }
}

// ================= O2 = (I - lam*L) @ O_cat : 8-wide MLP gather =================
__global__ void k_lapO(const float* __restrict__ lambda_lap) {
    int n = blockIdx.x * 8 + (threadIdx.x >> 5);
    int lane = threadIdx.x & 31;
    const float4* O = (const float4*)g_O;
    const int* cols = g_col + (size_t)n * MAXDEG;
    int dn = g_deg[n];
    float4 o = O[(size_t)n * 32 + lane];
    float4 s = make_float4(0.f, 0.f, 0.f, 0.f);
    int c = 0;
    for (; c + 8 <= dn; c += 8) {
        float4 v0 = O[(size_t)cols[c] * 32 + lane];
        float4 v1 = O[(size_t)cols[c + 1] * 32 + lane];
        float4 v2 = O[(size_t)cols[c + 2] * 32 + lane];
        float4 v3 = O[(size_t)cols[c + 3] * 32 + lane];
        float4 v4 = O[(size_t)cols[c + 4] * 32 + lane];
        float4 v5 = O[(size_t)cols[c + 5] * 32 + lane];
        float4 v6 = O[(size_t)cols[c + 6] * 32 + lane];
        float4 v7 = O[(size_t)cols[c + 7] * 32 + lane];
        s.x += ((v0.x + v1.x) + (v2.x + v3.x)) + ((v4.x + v5.x) + (v6.x + v7.x));
        s.y += ((v0.y + v1.y) + (v2.y + v3.y)) + ((v4.y + v5.y) + (v6.y + v7.y));
        s.z += ((v0.z + v1.z) + (v2.z + v3.z)) + ((v4.z + v5.z) + (v6.z + v7.z));
        s.w += ((v0.w + v1.w) + (v2.w + v3.w)) + ((v4.w + v5.w) + (v6.w + v7.w));
    }
    for (; c < dn; c++) {
        float4 v = O[(size_t)cols[c] * 32 + lane];
        s.x += v.x; s.y += v.y; s.z += v.z; s.w += v.w;
    }
    float lam = lambda_lap[0];
    float fd = (float)dn;
    float4 r;
    r.x = o.x - lam * (fd * o.x - s.x);
    r.y = o.y - lam * (fd * o.y - s.y);
    r.z = o.z - lam * (fd * o.z - s.z);
    r.w = o.w - lam * (fd * o.w - s.w);
    ((float4*)g_O2)[(size_t)n * 32 + lane] = r;
}

// ================= H_out = softthresh(hops0 + ETA * O2 @ Wc) =================
__global__ void k_HoutG(const float* __restrict__ hops,
                        const float* __restrict__ threshold,
                        float* __restrict__ out) {
    __shared__ float as[32][33];
    __shared__ float ws[32][33];
    int n0 = blockIdx.x * 32, d0 = blockIdx.y * 32;
    int lane = threadIdx.x & 31;
    int row = threadIdx.x >> 5;
    float acc[4] = {0.f, 0.f, 0.f, 0.f};
    for (int cc = 0; cc < K * S; cc += 32) {
#pragma unroll
        for (int i = 0; i < 4; i++) {
            int r = row + i * 8;
            as[r][lane] = g_O2[(size_t)(n0 + r) * (K * S) + cc + lane];
            ws[r][lane] = g_Wc[(size_t)(cc + r) * D + d0 + lane];
        }
        __syncthreads();
#pragma unroll
        for (int dd = 0; dd < 32; dd++) {
            float wv = ws[dd][lane];
#pragma unroll
            for (int i = 0; i < 4; i++) acc[i] += as[row * 4 + i][dd] * wv;
        }
        __syncthreads();
    }
    float th = threshold[d0 + lane];
#pragma unroll
    for (int i = 0; i < 4; i++) {
        int n = n0 + row * 4 + i;
        float hh = hops[(size_t)n * D + d0 + lane] + ETA * acc[i];
        float ab = fabsf(hh) - th;
        out[(size_t)n * D + d0 + lane] = (ab > 0.f) ? copysignf(ab, hh) : 0.f;
    }
}

// ================= lap_smooth partials (symmetric half, 8-wide MLP) + fused final =================
__global__ void k_lapF(const float* __restrict__ Hout, const float* __restrict__ hw,
                       float* __restrict__ out, int out_size) {
    __shared__ int hd[4];
    if (threadIdx.x < 4) {
        int nn = blockIdx.x * 4 + threadIdx.x;
        const int* cc = g_col + (size_t)nn * MAXDEG;
        int lo = 0, hi = g_deg[nn];
        while (lo < hi) {
            int mid = (lo + hi) >> 1;
            if (cc[mid] < nn) lo = mid + 1; else hi = mid;
        }
        hd[threadIdx.x] = lo;
    }
    __syncthreads();
    int g = threadIdx.x >> 6;
    int n = blockIdx.x * 4 + g;
    int t = threadIdx.x & 63;
    const float4* H = (const float4*)Hout;
    const int* cols = g_col + (size_t)n * MAXDEG;
    int dn = g_deg[n];
    int hn = hd[g];
    float4 h = H[(size_t)n * 64 + t];
    float4 vs = make_float4(0.f, 0.f, 0.f, 0.f);
    int c = 0;
    for (; c + 8 <= hn; c += 8) {
        float4 v0 = H[(size_t)cols[c] * 64 + t];
        float4 v1 = H[(size_t)cols[c + 1] * 64 + t];
        float4 v2 = H[(size_t)cols[c + 2] * 64 + t];
        float4 v3 = H[(size_t)cols[c + 3] * 64 + t];
        float4 v4 = H[(size_t)cols[c + 4] * 64 + t];
        float4 v5 = H[(size_t)cols[c + 5] * 64 + t];
        float4 v6 = H[(size_t)cols[c + 6] * 64 + t];
        float4 v7 = H[(size_t)cols[c + 7] * 64 + t];
        vs.x += ((v0.x + v1.x) + (v2.x + v3.x)) + ((v4.x + v5.x) + (v6.x + v7.x));
        vs.y += ((v0.y + v1.y) + (v2.y + v3.y)) + ((v4.y + v5.y) + (v6.y + v7.y));
        vs.z += ((v0.z + v1.z) + (v2.z + v3.z)) + ((v4.z + v5.z) + (v6.z + v7.z));
        vs.w += ((v0.w + v1.w) + (v2.w + v3.w)) + ((v4.w + v5.w) + (v6.w + v7.w));
    }
    for (; c < hn; c++) {
        float4 v = H[(size_t)cols[c] * 64 + t];
        vs.x += v.x; vs.y += v.y; vs.z += v.z; vs.w += v.w;
    }
    float fd = (float)dn - 1.0f;
    float dot = fd * (h.x * h.x + h.y * h.y + h.z * h.z + h.w * h.w)
              - 2.0f * (h.x * vs.x + h.y * vs.y + h.z * vs.z + h.w * vs.w);
    dot = warpSum(dot);
    __shared__ float sred[8];
    if ((threadIdx.x & 31) == 0) sred[threadIdx.x >> 5] = dot;
    __syncthreads();
    if (threadIdx.x < 4)
        g_partials[blockIdx.x * 4 + threadIdx.x] =
            sred[threadIdx.x * 2] + sred[threadIdx.x * 2 + 1];

    __threadfence();
    __shared__ int isLast;
    if (threadIdx.x == 0) {
        int v = atomicAdd(&g_ctr, 1);
        isLast = (v == (int)gridDim.x - 1) ? 1 : 0;
        if (isLast) atomicExch(&g_ctr, 0);
    }
    __syncthreads();
    if (!isLast) return;
    __threadfence();

    float v = 0.f;
    for (int i = threadIdx.x; i < N; i += 256) v += g_partials[i];
    __shared__ float red2[256];
    red2[threadIdx.x] = v;
    __syncthreads();
    for (int off = 128; off > 0; off >>= 1) {
        if (threadIdx.x < off) red2[threadIdx.x] += red2[threadIdx.x + off];
        __syncthreads();
    }
    if (threadIdx.x == 0) {
        float orth = 0.f;
        for (int p = 0; p < 10; p++) orth += g_orth[p];
        float m = fmaxf(fmaxf(hw[0], hw[1]), fmaxf(hw[2], hw[3]));
        float e0 = expf(hw[0] - m), e1 = expf(hw[1] - m);
        float e2 = expf(hw[2] - m), e3 = expf(hw[3] - m);
        float s = e0 + e1 + e2 + e3;
        int base = N * D;
        if (base < out_size) out[base] = orth;
        if (base + 1 < out_size) out[base + 1] = red2[0];
        if (base + 2 < out_size) out[base + 2] = e0 / s;
        if (base + 3 < out_size) out[base + 3] = e1 / s;
        if (base + 4 < out_size) out[base + 4] = e2 / s;
        if (base + 5 < out_size) out[base + 5] = e3 / s;
    }
}

// ---------------- launch ----------------
extern "C" void kernel_launch(void* const* d_in, const int* in_sizes, int n_in,
                              void* d_out, int out_size) {
    const float* hops      = (const float*)d_in[0];
    const float* adj       = (const float*)d_in[1];
    const float* U         = (const float*)d_in[3];
    const float* hw        = (const float*)d_in[4];
    const float* threshold = (const float*)d_in[5];
    const float* lam       = (const float*)d_in[6];
    float* out = (float*)d_out;

    k_mega1<<<810, 256>>>(hops, adj, U, hw);
    k_gram<<<128, 1024>>>();
    {
        dim3 g(N / 32, K);
        k_MZ<<<g, 256>>>();
    }
    k_attn<<<(2 * K * N) / 8, 256>>>();
    k_lapO<<<N / 8, 256>>>(lam);
    {
        dim3 g(N / 32, D / 32);
        k_HoutG<<<g, 256>>>(hops, threshold, out);
    }
    k_lapF<<<N / 4, 256>>>(out, hw, out, out_size);
}

// round 16
// speedup vs baseline: 1.0301x; 1.0301x over previous
#include <cuda_runtime.h>
#include <math.h>

#define K 4
#define N 4096
#define D 256
#define S 32
#define MAXDEG 512
#define ETA 0.5f
#define COEFF 0.03125f   // S/(N*EPS^2)

// ---------------- scratch ----------------
__device__ float g_Zt[K * N * S];        // [k][n][s]
__device__ float g_MZt[K * N * S];       // [k][n][s]
__device__ float g_Minv[K * S * S];
__device__ float g_O[(size_t)N * (K * S)];   // O_cat: [n][k*S+s]
__device__ float g_O2[(size_t)N * (K * S)];  // (I - lam*L) @ O_cat
__device__ float g_Wc[K * S * D];        // w_k * U[k]^T : [k*S+s][d]
__device__ float g_gramP[K * 32 * S * S];
__device__ int   g_col[(size_t)N * MAXDEG];
__device__ int   g_deg[N];
__device__ float g_partials[N];
__device__ float g_orth[10];
__device__ int   g_ctr;       // zero-init; self-resetting
__device__ int   g_ctrK[K];   // zero-init; self-resetting

__device__ __forceinline__ float warpSum(float v) {
    v += __shfl_xor_sync(0xffffffffu, v, 16);
    v += __shfl_xor_sync(0xffffffffu, v, 8);
    v += __shfl_xor_sync(0xffffffffu, v, 4);
    v += __shfl_xor_sync(0xffffffffu, v, 2);
    v += __shfl_xor_sync(0xffffffffu, v, 1);
    return v;
}

__device__ __forceinline__ float ex2fast(float x) {
    float r;
    asm("ex2.approx.f32 %0, %1;" : "=f"(r) : "f"(x));
    return r;
}

// ================= mega kernel 1: Z (0..255) | CSR (256..767) | Wc (768..799) | orth (800..809) =================
__global__ void __launch_bounds__(256) k_mega1(const float* __restrict__ hops,
                                               const float* __restrict__ adj,
                                               const float* __restrict__ U,
                                               const float* __restrict__ hw) {
    __shared__ float sm[6528];
    int bx = blockIdx.x;
    int tid = threadIdx.x;

    if (bx < 256) {
        // ---------- Z = hops[k] @ U[k] : 64n x 32s tile, double-buffered ----------
        int k = bx >> 6;
        int n0 = (bx & 63) * 64;
        float* hsT0 = sm;            // 32*66
        float* hsT1 = sm + 2112;
        float* us0  = sm + 4224;     // 32*36
        float* us1  = sm + 5376;
        int ny = tid >> 3;
        int sx = (tid & 7) * 4;
        int rowq = tid >> 3;
        int q = tid & 7;
        const float* Hb = hops + ((size_t)k * N + n0) * D;
        const float* Ub = U + (size_t)k * D * S;

        float4 h0, h1, u0;
        h0 = *(const float4*)&Hb[(size_t)rowq * D + q * 4];
        h1 = *(const float4*)&Hb[(size_t)(rowq + 32) * D + q * 4];
        u0 = *(const float4*)&Ub[(size_t)rowq * S + q * 4];
        {
            float* hb = hsT0;
            hb[(q * 4 + 0) * 66 + rowq] = h0.x;
            hb[(q * 4 + 1) * 66 + rowq] = h0.y;
            hb[(q * 4 + 2) * 66 + rowq] = h0.z;
            hb[(q * 4 + 3) * 66 + rowq] = h0.w;
            hb[(q * 4 + 0) * 66 + rowq + 32] = h1.x;
            hb[(q * 4 + 1) * 66 + rowq + 32] = h1.y;
            hb[(q * 4 + 2) * 66 + rowq + 32] = h1.z;
            hb[(q * 4 + 3) * 66 + rowq + 32] = h1.w;
            *(float4*)&us0[rowq * 36 + q * 4] = u0;
        }
        __syncthreads();

        float a0x = 0.f, a0y = 0.f, a0z = 0.f, a0w = 0.f;
        float a1x = 0.f, a1y = 0.f, a1z = 0.f, a1w = 0.f;

        for (int ch = 0; ch < 8; ch++) {
            const float* hb = (ch & 1) ? hsT1 : hsT0;
            const float* ub = (ch & 1) ? us1 : us0;
            if (ch < 7) {
                int dc = (ch + 1) * 32;
                h0 = *(const float4*)&Hb[(size_t)rowq * D + dc + q * 4];
                h1 = *(const float4*)&Hb[(size_t)(rowq + 32) * D + dc + q * 4];
                u0 = *(const float4*)&Ub[(size_t)(dc + rowq) * S + q * 4];
            }
#pragma unroll
            for (int d = 0; d < 32; d++) {
                float2 h = *(const float2*)&hb[d * 66 + ny * 2];
                float4 u = *(const float4*)&ub[d * 36 + sx];
                a0x += h.x * u.x; a0y += h.x * u.y; a0z += h.x * u.z; a0w += h.x * u.w;
                a1x += h.y * u.x; a1y += h.y * u.y; a1z += h.y * u.z; a1w += h.y * u.w;
            }
            if (ch < 7) {
                float* hb2 = (ch & 1) ? hsT0 : hsT1;
                float* ub2 = (ch & 1) ? us0 : us1;
                hb2[(q * 4 + 0) * 66 + rowq] = h0.x;
                hb2[(q * 4 + 1) * 66 + rowq] = h0.y;
                hb2[(q * 4 + 2) * 66 + rowq] = h0.z;
                hb2[(q * 4 + 3) * 66 + rowq] = h0.w;
                hb2[(q * 4 + 0) * 66 + rowq + 32] = h1.x;
                hb2[(q * 4 + 1) * 66 + rowq + 32] = h1.y;
                hb2[(q * 4 + 2) * 66 + rowq + 32] = h1.z;
                hb2[(q * 4 + 3) * 66 + rowq + 32] = h1.w;
                *(float4*)&ub2[rowq * 36 + q * 4] = u0;
            }
            __syncthreads();
        }
        size_t base = ((size_t)k * N + n0 + ny * 2) * S + sx;
        *(float4*)&g_Zt[base] = make_float4(a0x, a0y, a0z, a0w);
        *(float4*)&g_Zt[base + S] = make_float4(a1x, a1y, a1z, a1w);
    } else if (bx < 768) {
        // ---------- CSR build (warp per row, float4 + 4 ballots per 128 cols) ----------
        int n = (bx - 256) * 8 + (tid >> 5);
        int lane = tid & 31;
        const float4* row = (const float4*)(adj + (size_t)n * N);
        int* dst = g_col + (size_t)n * MAXDEG;
        unsigned lm = (1u << lane) - 1u;
        int cnt = 0;
        for (int base = 0; base < N / 4; base += 32) {
            float4 a = row[base + lane];
            unsigned m0 = __ballot_sync(0xffffffffu, a.x != 0.0f);
            unsigned m1 = __ballot_sync(0xffffffffu, a.y != 0.0f);
            unsigned m2 = __ballot_sync(0xffffffffu, a.z != 0.0f);
            unsigned m3 = __ballot_sync(0xffffffffu, a.w != 0.0f);
            int pre = cnt + __popc(m0 & lm) + __popc(m1 & lm)
                          + __popc(m2 & lm) + __popc(m3 & lm);
            int j0 = (base + lane) * 4;
            if (a.x != 0.0f) dst[pre] = j0;
            int o1 = pre + ((m0 >> lane) & 1);
            if (a.y != 0.0f) dst[o1] = j0 + 1;
            int o2 = o1 + ((m1 >> lane) & 1);
            if (a.z != 0.0f) dst[o2] = j0 + 2;
            int o3 = o2 + ((m2 >> lane) & 1);
            if (a.w != 0.0f) dst[o3] = j0 + 3;
            cnt += __popc(m0) + __popc(m1) + __popc(m2) + __popc(m3);
        }
        if (lane == 0) g_deg[n] = min(cnt, MAXDEG);
    } else if (bx < 800) {
        // ---------- Wc[k*S+s][d] = w_k * U[k][d][s] ----------
        float m = fmaxf(fmaxf(hw[0], hw[1]), fmaxf(hw[2], hw[3]));
        float e0 = expf(hw[0] - m), e1 = expf(hw[1] - m);
        float e2 = expf(hw[2] - m), e3 = expf(hw[3] - m);
        float sum = e0 + e1 + e2 + e3;
        int base = ((bx - 768) * 256 + tid) * 4;
        float4 u4 = *(const float4*)&U[base];
        int k = base / (D * S);
        int rem = base % (D * S);
        int d = rem / S;
        int s = rem % S;
        float wk = (k == 0 ? e0 : k == 1 ? e1 : k == 2 ? e2 : e3) / sum;
        g_Wc[(k * S + s + 0) * D + d] = wk * u4.x;
        g_Wc[(k * S + s + 1) * D + d] = wk * u4.y;
        g_Wc[(k * S + s + 2) * D + d] = wk * u4.z;
        g_Wc[(k * S + s + 3) * D + d] = wk * u4.w;
    } else {
        // ---------- orth pair (s,t) dots; 4 t per thread ----------
        const int kk[10] = {0, 0, 0, 0, 1, 1, 1, 2, 2, 3};
        const int ll[10] = {0, 1, 2, 3, 1, 2, 3, 2, 3, 3};
        int p = bx - 800;
        int k = kk[p], l = ll[p];
        int s = tid >> 3;
        int t0 = (tid & 7) * 4;
        float* uk = sm;
        float* ul = sm + 2048;
        float* red = sm + 4096;
        float c0 = 0.f, c1 = 0.f, c2 = 0.f, c3 = 0.f;
        for (int dc = 0; dc < D; dc += 64) {
            for (int i = tid; i < 2048; i += 256) {
                uk[i] = U[((size_t)k * D + dc) * S + i];
                ul[i] = U[((size_t)l * D + dc) * S + i];
            }
            __syncthreads();
#pragma unroll 8
            for (int d = 0; d < 64; d++) {
                float a = uk[d * 32 + s];
                float4 b = *(const float4*)&ul[d * 32 + t0];
                c0 += a * b.x; c1 += a * b.y; c2 += a * b.z; c3 += a * b.w;
            }
            __syncthreads();
        }
        if (k == l) {
            if (s == t0 + 0) c0 -= 1.0f;
            if (s == t0 + 1) c1 -= 1.0f;
            if (s == t0 + 2) c2 -= 1.0f;
            if (s == t0 + 3) c3 -= 1.0f;
        }
        red[tid] = (c0 * c0 + c1 * c1) + (c2 * c2 + c3 * c3);
        __syncthreads();
        for (int off = 128; off > 0; off >>= 1) {
            if (tid < off) red[tid] += red[tid + off];
            __syncthreads();
        }
        if (tid == 0) g_orth[p] = red[0];
    }
}

// ================= gram partials + last-block-per-k inversion =================
__global__ void __launch_bounds__(1024) k_gram(void) {
    __shared__ float sm[4224];
    int tid = threadIdx.x;
    int k = blockIdx.x >> 5;
    int chunk = blockIdx.x & 31;
    float* zs = sm;
    const float4* Z4 = (const float4*)(g_Zt + ((size_t)k * N + chunk * 128) * S);
    ((float4*)zs)[tid] = Z4[tid];
    __syncthreads();
    int s = tid >> 5, t = tid & 31;
    float g0 = 0.f, g1 = 0.f, g2 = 0.f, g3 = 0.f;
#pragma unroll 8
    for (int n = 0; n < 128; n += 4) {
        g0 += zs[(n + 0) * 32 + s] * zs[(n + 0) * 32 + t];
        g1 += zs[(n + 1) * 32 + s] * zs[(n + 1) * 32 + t];
        g2 += zs[(n + 2) * 32 + s] * zs[(n + 2) * 32 + t];
        g3 += zs[(n + 3) * 32 + s] * zs[(n + 3) * 32 + t];
    }
    g_gramP[(((size_t)k * 32 + chunk) * S + s) * S + t] = (g0 + g1) + (g2 + g3);
    __threadfence();
    __shared__ int isLast;
    if (tid == 0) {
        int v = atomicAdd(&g_ctrK[k], 1);
        isLast = (v == 31);
        if (v == 31) atomicExch(&g_ctrK[k], 0);
    }
    __syncthreads();
    if (!isLast) return;
    __threadfence();
    float g = 0.f;
    for (int c = 0; c < 32; c++)
        g += g_gramP[(((size_t)k * 32 + c) * S + s) * S + t];
    float (*aug)[66] = (float(*)[66])sm;
    __syncthreads();
    aug[s][t] = (s == t ? 1.0f : 0.0f) + COEFF * g;
    aug[s][32 + t] = (s == t ? 1.0f : 0.0f);
    __syncthreads();
    int r0 = tid >> 6, c0 = tid & 63;
    int tid2 = tid + 1024;
    int r1 = tid2 >> 6, c1 = tid2 & 63;
    for (int p = 0; p < 32; p++) {
        float inv = 1.0f / aug[p][p];
        float f0 = aug[r0][p], pr0 = aug[p][c0];
        float f1 = aug[r1][p], pr1 = aug[p][c1];
        __syncthreads();
        if (r0 == p) aug[p][c0] = pr0 * inv;
        else         aug[r0][c0] -= f0 * inv * pr0;
        if (r1 == p) aug[p][c1] = pr1 * inv;
        else         aug[r1][c1] -= f1 * inv * pr1;
        __syncthreads();
    }
    g_Minv[k * S * S + s * S + t] = aug[s][32 + t];
}

// ================= MZt = Minv[k] @ Zt rows : conflict-free, 4 rows/warp =================
__global__ void k_MZ(void) {
    __shared__ float Msh[32 * 33];
    __shared__ float zsh[32 * 33];
    int k = blockIdx.y;
    int n0 = blockIdx.x * 32;
    int tid = threadIdx.x;
    int w = tid >> 5;
    int lane = tid & 31;
    {
        float4 v = ((const float4*)(g_Minv + k * S * S))[tid];
        int r = (tid * 4) >> 5;
        int c = (tid * 4) & 31;
        float* dst = &Msh[r * 33 + c];
        dst[0] = v.x; dst[1] = v.y; dst[2] = v.z; dst[3] = v.w;
    }
    {
        int r = tid >> 3, q = tid & 7;
        float4 v = *(const float4*)&g_Zt[((size_t)k * N + n0 + r) * S + q * 4];
        float* dst = &zsh[r * 33 + q * 4];
        dst[0] = v.x; dst[1] = v.y; dst[2] = v.z; dst[3] = v.w;
    }
    __syncthreads();
    float a0 = 0.f, a1 = 0.f, a2 = 0.f, a3 = 0.f;
    const float* z0 = &zsh[(w * 4 + 0) * 33];
    const float* z1 = &zsh[(w * 4 + 1) * 33];
    const float* z2 = &zsh[(w * 4 + 2) * 33];
    const float* z3 = &zsh[(w * 4 + 3) * 33];
#pragma unroll
    for (int t = 0; t < 32; t++) {
        float mv = Msh[t * 33 + lane];
        a0 += mv * z0[t];
        a1 += mv * z1[t];
        a2 += mv * z2[t];
        a3 += mv * z3[t];
    }
    size_t base = ((size_t)k * N + n0 + w * 4) * S + lane;
    g_MZt[base] = a0;
    g_MZt[base + S] = a1;
    g_MZt[base + 2 * S] = a2;
    g_MZt[base + 3 * S] = a3;
}

// ================= sparse attention: 4 lanes/row, pipelined column prefetch =================
__global__ void __launch_bounds__(256) k_attn(void) {
    int w = threadIdx.x >> 5;
    int lane = threadIdx.x & 31;
    int gwarp = blockIdx.x * 8 + w;
    int k = gwarp >> 12;
    int n = gwarp & (N - 1);
    const float* __restrict__ MZ = g_MZt + (size_t)k * N * S;
    const int* __restrict__ cols = g_col + (size_t)n * MAXDEG;
    int dn = g_deg[n];
    int f2 = lane & 3;
    int rr = lane >> 2;
    const float LOG2E = 1.4426950408889634f;
    const float* qp = &g_Zt[((size_t)k * N + n) * S + f2 * 8];
    float4 qa = *(const float4*)&qp[0];
    float4 qb = *(const float4*)&qp[4];
    qa.x *= LOG2E; qa.y *= LOG2E; qa.z *= LOG2E; qa.w *= LOG2E;
    qb.x *= LOG2E; qb.y *= LOG2E; qb.z *= LOG2E; qb.w *= LOG2E;

    float4 aa = make_float4(0.f, 0.f, 0.f, 0.f);
    float4 ab = make_float4(0.f, 0.f, 0.f, 0.f);
    float l = 0.f;

    // prologue: indices for chunk 0
    int j0 = (rr < dn) ? cols[rr] : 0;
    int j1 = (8 + rr < dn) ? cols[8 + rr] : 0;

    for (int c0 = 0; c0 < dn; c0 += 16) {
        const float* vp0 = &MZ[(size_t)j0 * S + f2 * 8];
        const float* vp1 = &MZ[(size_t)j1 * S + f2 * 8];
        float4 va0 = *(const float4*)&vp0[0];
        float4 vb0 = *(const float4*)&vp0[4];
        float4 va1 = *(const float4*)&vp1[0];
        float4 vb1 = *(const float4*)&vp1[4];
        int nr0 = c0 + 16 + rr, nr1 = c0 + 24 + rr;
        int jn0 = (nr0 < dn) ? cols[nr0] : 0;
        int jn1 = (nr1 < dn) ? cols[nr1] : 0;

        bool in0 = (c0 + rr < dn);
        bool in1 = (c0 + 8 + rr < dn);

        float p0 = qa.x * va0.x + qa.y * va0.y + qa.z * va0.z + qa.w * va0.w
                 + qb.x * vb0.x + qb.y * vb0.y + qb.z * vb0.z + qb.w * vb0.w;
        float p1 = qa.x * va1.x + qa.y * va1.y + qa.z * va1.z + qa.w * va1.w
                 + qb.x * vb1.x + qb.y * vb1.y + qb.z * vb1.z + qb.w * vb1.w;
        p0 += __shfl_xor_sync(0xffffffffu, p0, 1);
        p1 += __shfl_xor_sync(0xffffffffu, p1, 1);
        p0 += __shfl_xor_sync(0xffffffffu, p0, 2);
        p1 += __shfl_xor_sync(0xffffffffu, p1, 2);
        p0 = in0 ? p0 : -1e30f;
        p1 = in1 ? p1 : -1e30f;
        float e0 = ex2fast(p0);
        float e1 = ex2fast(p1);
        l += e0 + e1;
        aa.x += e0 * va0.x; aa.y += e0 * va0.y; aa.z += e0 * va0.z; aa.w += e0 * va0.w;
        ab.x += e0 * vb0.x; ab.y += e0 * vb0.y; ab.z += e0 * vb0.z; ab.w += e0 * vb0.w;
        aa.x += e1 * va1.x; aa.y += e1 * va1.y; aa.z += e1 * va1.z; aa.w += e1 * va1.w;
        ab.x += e1 * vb1.x; ab.y += e1 * vb1.y; ab.z += e1 * vb1.z; ab.w += e1 * vb1.w;

        j0 = jn0; j1 = jn1;
    }

#pragma unroll
    for (int off = 4; off <= 16; off <<= 1) {
        aa.x += __shfl_xor_sync(0xffffffffu, aa.x, off);
        aa.y += __shfl_xor_sync(0xffffffffu, aa.y, off);
        aa.z += __shfl_xor_sync(0xffffffffu, aa.z, off);
        aa.w += __shfl_xor_sync(0xffffffffu, aa.w, off);
        ab.x += __shfl_xor_sync(0xffffffffu, ab.x, off);
        ab.y += __shfl_xor_sync(0xffffffffu, ab.y, off);
        ab.z += __shfl_xor_sync(0xffffffffu, ab.z, off);
        ab.w += __shfl_xor_sync(0xffffffffu, ab.w, off);
        l    += __shfl_xor_sync(0xffffffffu, l, off);
    }
    if (rr == 0) {
        float inv = 1.0f / l;
        float* dst = &g_O[(size_t)n * (K * S) + k * S + f2 * 8];
        *(float4*)&dst[0] = make_float4(aa.x * inv, aa.y * inv, aa.z * inv, aa.w * inv);
        *(float4*)&dst[4] = make_float4(ab.x * inv, ab.y * inv, ab.z * inv, ab.w * inv);
    }
}

// ================= O2 = (I - lam*L) @ O_cat : 8-wide MLP gather =================
__global__ void k_lapO(const float* __restrict__ lambda_lap) {
    int n = blockIdx.x * 8 + (threadIdx.x >> 5);
    int lane = threadIdx.x & 31;
    const float4* O = (const float4*)g_O;
    const int* cols = g_col + (size_t)n * MAXDEG;
    int dn = g_deg[n];
    float4 o = O[(size_t)n * 32 + lane];
    float4 s = make_float4(0.f, 0.f, 0.f, 0.f);
    int c = 0;
    for (; c + 8 <= dn; c += 8) {
        float4 v0 = O[(size_t)cols[c] * 32 + lane];
        float4 v1 = O[(size_t)cols[c + 1] * 32 + lane];
        float4 v2 = O[(size_t)cols[c + 2] * 32 + lane];
        float4 v3 = O[(size_t)cols[c + 3] * 32 + lane];
        float4 v4 = O[(size_t)cols[c + 4] * 32 + lane];
        float4 v5 = O[(size_t)cols[c + 5] * 32 + lane];
        float4 v6 = O[(size_t)cols[c + 6] * 32 + lane];
        float4 v7 = O[(size_t)cols[c + 7] * 32 + lane];
        s.x += ((v0.x + v1.x) + (v2.x + v3.x)) + ((v4.x + v5.x) + (v6.x + v7.x));
        s.y += ((v0.y + v1.y) + (v2.y + v3.y)) + ((v4.y + v5.y) + (v6.y + v7.y));
        s.z += ((v0.z + v1.z) + (v2.z + v3.z)) + ((v4.z + v5.z) + (v6.z + v7.z));
        s.w += ((v0.w + v1.w) + (v2.w + v3.w)) + ((v4.w + v5.w) + (v6.w + v7.w));
    }
    for (; c < dn; c++) {
        float4 v = O[(size_t)cols[c] * 32 + lane];
        s.x += v.x; s.y += v.y; s.z += v.z; s.w += v.w;
    }
    float lam = lambda_lap[0];
    float fd = (float)dn;
    float4 r;
    r.x = o.x - lam * (fd * o.x - s.x);
    r.y = o.y - lam * (fd * o.y - s.y);
    r.z = o.z - lam * (fd * o.z - s.z);
    r.w = o.w - lam * (fd * o.w - s.w);
    ((float4*)g_O2)[(size_t)n * 32 + lane] = r;
}

// ================= H_out = softthresh(hops0 + ETA * O2 @ Wc) =================
__global__ void k_HoutG(const float* __restrict__ hops,
                        const float* __restrict__ threshold,
                        float* __restrict__ out) {
    __shared__ float as[32][33];
    __shared__ float ws[32][33];
    int n0 = blockIdx.x * 32, d0 = blockIdx.y * 32;
    int lane = threadIdx.x & 31;
    int row = threadIdx.x >> 5;
    float acc[4] = {0.f, 0.f, 0.f, 0.f};
    for (int cc = 0; cc < K * S; cc += 32) {
#pragma unroll
        for (int i = 0; i < 4; i++) {
            int r = row + i * 8;
            as[r][lane] = g_O2[(size_t)(n0 + r) * (K * S) + cc + lane];
            ws[r][lane] = g_Wc[(size_t)(cc + r) * D + d0 + lane];
        }
        __syncthreads();
#pragma unroll
        for (int dd = 0; dd < 32; dd++) {
            float wv = ws[dd][lane];
#pragma unroll
            for (int i = 0; i < 4; i++) acc[i] += as[row * 4 + i][dd] * wv;
        }
        __syncthreads();
    }
    float th = threshold[d0 + lane];
#pragma unroll
    for (int i = 0; i < 4; i++) {
        int n = n0 + row * 4 + i;
        float hh = hops[(size_t)n * D + d0 + lane] + ETA * acc[i];
        float ab = fabsf(hh) - th;
        out[(size_t)n * D + d0 + lane] = (ab > 0.f) ? copysignf(ab, hh) : 0.f;
    }
}

// ================= lap_smooth partials (symmetric half, 8-wide MLP) + fused final =================
__global__ void k_lapF(const float* __restrict__ Hout, const float* __restrict__ hw,
                       float* __restrict__ out, int out_size) {
    __shared__ int hd[4];
    if (threadIdx.x < 4) {
        int nn = blockIdx.x * 4 + threadIdx.x;
        const int* cc = g_col + (size_t)nn * MAXDEG;
        int lo = 0, hi = g_deg[nn];
        while (lo < hi) {
            int mid = (lo + hi) >> 1;
            if (cc[mid] < nn) lo = mid + 1; else hi = mid;
        }
        hd[threadIdx.x] = lo;
    }
    __syncthreads();
    int g = threadIdx.x >> 6;
    int n = blockIdx.x * 4 + g;
    int t = threadIdx.x & 63;
    const float4* H = (const float4*)Hout;
    const int* cols = g_col + (size_t)n * MAXDEG;
    int dn = g_deg[n];
    int hn = hd[g];
    float4 h = H[(size_t)n * 64 + t];
    float4 vs = make_float4(0.f, 0.f, 0.f, 0.f);
    int c = 0;
    for (; c + 8 <= hn; c += 8) {
        float4 v0 = H[(size_t)cols[c] * 64 + t];
        float4 v1 = H[(size_t)cols[c + 1] * 64 + t];
        float4 v2 = H[(size_t)cols[c + 2] * 64 + t];
        float4 v3 = H[(size_t)cols[c + 3] * 64 + t];
        float4 v4 = H[(size_t)cols[c + 4] * 64 + t];
        float4 v5 = H[(size_t)cols[c + 5] * 64 + t];
        float4 v6 = H[(size_t)cols[c + 6] * 64 + t];
        float4 v7 = H[(size_t)cols[c + 7] * 64 + t];
        vs.x += ((v0.x + v1.x) + (v2.x + v3.x)) + ((v4.x + v5.x) + (v6.x + v7.x));
        vs.y += ((v0.y + v1.y) + (v2.y + v3.y)) + ((v4.y + v5.y) + (v6.y + v7.y));
        vs.z += ((v0.z + v1.z) + (v2.z + v3.z)) + ((v4.z + v5.z) + (v6.z + v7.z));
        vs.w += ((v0.w + v1.w) + (v2.w + v3.w)) + ((v4.w + v5.w) + (v6.w + v7.w));
    }
    for (; c < hn; c++) {
        float4 v = H[(size_t)cols[c] * 64 + t];
        vs.x += v.x; vs.y += v.y; vs.z += v.z; vs.w += v.w;
    }
    float fd = (float)dn - 1.0f;
    float dot = fd * (h.x * h.x + h.y * h.y + h.z * h.z + h.w * h.w)
              - 2.0f * (h.x * vs.x + h.y * vs.y + h.z * vs.z + h.w * vs.w);
    dot = warpSum(dot);
    __shared__ float sred[8];
    if ((threadIdx.x & 31) == 0) sred[threadIdx.x >> 5] = dot;
    __syncthreads();
    if (threadIdx.x < 4)
        g_partials[blockIdx.x * 4 + threadIdx.x] =
            sred[threadIdx.x * 2] + sred[threadIdx.x * 2 + 1];

    __threadfence();
    __shared__ int isLast;
    if (threadIdx.x == 0) {
        int v = atomicAdd(&g_ctr, 1);
        isLast = (v == (int)gridDim.x - 1) ? 1 : 0;
        if (isLast) atomicExch(&g_ctr, 0);
    }
    __syncthreads();
    if (!isLast) return;
    __threadfence();

    float v = 0.f;
    for (int i = threadIdx.x; i < N; i += 256) v += g_partials[i];
    __shared__ float red2[256];
    red2[threadIdx.x] = v;
    __syncthreads();
    for (int off = 128; off > 0; off >>= 1) {
        if (threadIdx.x < off) red2[threadIdx.x] += red2[threadIdx.x + off];
        __syncthreads();
    }
    if (threadIdx.x == 0) {
        float orth = 0.f;
        for (int p = 0; p < 10; p++) orth += g_orth[p];
        float m = fmaxf(fmaxf(hw[0], hw[1]), fmaxf(hw[2], hw[3]));
        float e0 = expf(hw[0] - m), e1 = expf(hw[1] - m);
        float e2 = expf(hw[2] - m), e3 = expf(hw[3] - m);
        float s = e0 + e1 + e2 + e3;
        int base = N * D;
        if (base < out_size) out[base] = orth;
        if (base + 1 < out_size) out[base + 1] = red2[0];
        if (base + 2 < out_size) out[base + 2] = e0 / s;
        if (base + 3 < out_size) out[base + 3] = e1 / s;
        if (base + 4 < out_size) out[base + 4] = e2 / s;
        if (base + 5 < out_size) out[base + 5] = e3 / s;
    }
}

// ---------------- launch ----------------
extern "C" void kernel_launch(void* const* d_in, const int* in_sizes, int n_in,
                              void* d_out, int out_size) {
    const float* hops      = (const float*)d_in[0];
    const float* adj       = (const float*)d_in[1];
    const float* U         = (const float*)d_in[3];
    const float* hw        = (const float*)d_in[4];
    const float* threshold = (const float*)d_in[5];
    const float* lam       = (const float*)d_in[6];
    float* out = (float*)d_out;

    k_mega1<<<810, 256>>>(hops, adj, U, hw);
    k_gram<<<128, 1024>>>();
    {
        dim3 g(N / 32, K);
        k_MZ<<<g, 256>>>();
    }
    k_attn<<<(K * N) / 8, 256>>>();
    k_lapO<<<N / 8, 256>>>(lam);
    {
        dim3 g(N / 32, D / 32);
        k_HoutG<<<g, 256>>>(hops, threshold, out);
    }
    k_lapF<<<N / 4, 256>>>(out, hw, out, out_size);
}

// round 17
// speedup vs baseline: 1.0480x; 1.0174x over previous
#include <cuda_runtime.h>
#include <math.h>

#define K 4
#define N 4096
#define D 256
#define S 32
#define MAXDEG 512
#define ETA 0.5f
#define COEFF 0.03125f   // S/(N*EPS^2)

// ---------------- scratch ----------------
__device__ float g_Zt[K * N * S];        // [k][n][s]
__device__ float g_Minv[K * S * S];
__device__ float g_O[(size_t)N * (K * S)];   // O_cat: [n][k*S+s]
__device__ float g_O2[(size_t)N * (K * S)];  // (I - lam*L) @ O_cat
__device__ float g_Wc[K * S * D];        // w_k * U[k]^T : [k*S+s][d]
__device__ float g_gramP[K * 32 * S * S];
__device__ int   g_col[(size_t)N * MAXDEG];
__device__ int   g_deg[N];
__device__ float g_partials[N];
__device__ float g_orth[10];
__device__ int   g_ctr;       // zero-init; self-resetting
__device__ int   g_ctrK[K];   // zero-init; self-resetting

__device__ __forceinline__ float warpSum(float v) {
    v += __shfl_xor_sync(0xffffffffu, v, 16);
    v += __shfl_xor_sync(0xffffffffu, v, 8);
    v += __shfl_xor_sync(0xffffffffu, v, 4);
    v += __shfl_xor_sync(0xffffffffu, v, 2);
    v += __shfl_xor_sync(0xffffffffu, v, 1);
    return v;
}

__device__ __forceinline__ float ex2fast(float x) {
    float r;
    asm("ex2.approx.f32 %0, %1;" : "=f"(r) : "f"(x));
    return r;
}

// ================= mega kernel 1: Z (0..255) | CSR (256..767) | Wc (768..799) | orth (800..809) =================
__global__ void __launch_bounds__(256) k_mega1(const float* __restrict__ hops,
                                               const float* __restrict__ adj,
                                               const float* __restrict__ U,
                                               const float* __restrict__ hw) {
    __shared__ float sm[6528];
    int bx = blockIdx.x;
    int tid = threadIdx.x;

    if (bx < 256) {
        // ---------- Z = hops[k] @ U[k] : 64n x 32s tile, double-buffered ----------
        int k = bx >> 6;
        int n0 = (bx & 63) * 64;
        float* hsT0 = sm;            // 32*66
        float* hsT1 = sm + 2112;
        float* us0  = sm + 4224;     // 32*36
        float* us1  = sm + 5376;
        int ny = tid >> 3;
        int sx = (tid & 7) * 4;
        int rowq = tid >> 3;
        int q = tid & 7;
        const float* Hb = hops + ((size_t)k * N + n0) * D;
        const float* Ub = U + (size_t)k * D * S;

        float4 h0, h1, u0;
        h0 = *(const float4*)&Hb[(size_t)rowq * D + q * 4];
        h1 = *(const float4*)&Hb[(size_t)(rowq + 32) * D + q * 4];
        u0 = *(const float4*)&Ub[(size_t)rowq * S + q * 4];
        {
            float* hb = hsT0;
            hb[(q * 4 + 0) * 66 + rowq] = h0.x;
            hb[(q * 4 + 1) * 66 + rowq] = h0.y;
            hb[(q * 4 + 2) * 66 + rowq] = h0.z;
            hb[(q * 4 + 3) * 66 + rowq] = h0.w;
            hb[(q * 4 + 0) * 66 + rowq + 32] = h1.x;
            hb[(q * 4 + 1) * 66 + rowq + 32] = h1.y;
            hb[(q * 4 + 2) * 66 + rowq + 32] = h1.z;
            hb[(q * 4 + 3) * 66 + rowq + 32] = h1.w;
            *(float4*)&us0[rowq * 36 + q * 4] = u0;
        }
        __syncthreads();

        float a0x = 0.f, a0y = 0.f, a0z = 0.f, a0w = 0.f;
        float a1x = 0.f, a1y = 0.f, a1z = 0.f, a1w = 0.f;

        for (int ch = 0; ch < 8; ch++) {
            const float* hb = (ch & 1) ? hsT1 : hsT0;
            const float* ub = (ch & 1) ? us1 : us0;
            if (ch < 7) {
                int dc = (ch + 1) * 32;
                h0 = *(const float4*)&Hb[(size_t)rowq * D + dc + q * 4];
                h1 = *(const float4*)&Hb[(size_t)(rowq + 32) * D + dc + q * 4];
                u0 = *(const float4*)&Ub[(size_t)(dc + rowq) * S + q * 4];
            }
#pragma unroll
            for (int d = 0; d < 32; d++) {
                float2 h = *(const float2*)&hb[d * 66 + ny * 2];
                float4 u = *(const float4*)&ub[d * 36 + sx];
                a0x += h.x * u.x; a0y += h.x * u.y; a0z += h.x * u.z; a0w += h.x * u.w;
                a1x += h.y * u.x; a1y += h.y * u.y; a1z += h.y * u.z; a1w += h.y * u.w;
            }
            if (ch < 7) {
                float* hb2 = (ch & 1) ? hsT0 : hsT1;
                float* ub2 = (ch & 1) ? us0 : us1;
                hb2[(q * 4 + 0) * 66 + rowq] = h0.x;
                hb2[(q * 4 + 1) * 66 + rowq] = h0.y;
                hb2[(q * 4 + 2) * 66 + rowq] = h0.z;
                hb2[(q * 4 + 3) * 66 + rowq] = h0.w;
                hb2[(q * 4 + 0) * 66 + rowq + 32] = h1.x;
                hb2[(q * 4 + 1) * 66 + rowq + 32] = h1.y;
                hb2[(q * 4 + 2) * 66 + rowq + 32] = h1.z;
                hb2[(q * 4 + 3) * 66 + rowq + 32] = h1.w;
                *(float4*)&ub2[rowq * 36 + q * 4] = u0;
            }
            __syncthreads();
        }
        size_t base = ((size_t)k * N + n0 + ny * 2) * S + sx;
        *(float4*)&g_Zt[base] = make_float4(a0x, a0y, a0z, a0w);
        *(float4*)&g_Zt[base + S] = make_float4(a1x, a1y, a1z, a1w);
    } else if (bx < 768) {
        // ---------- CSR build (warp per row, float4 + 4 ballots per 128 cols) ----------
        int n = (bx - 256) * 8 + (tid >> 5);
        int lane = tid & 31;
        const float4* row = (const float4*)(adj + (size_t)n * N);
        int* dst = g_col + (size_t)n * MAXDEG;
        unsigned lm = (1u << lane) - 1u;
        int cnt = 0;
        for (int base = 0; base < N / 4; base += 32) {
            float4 a = row[base + lane];
            unsigned m0 = __ballot_sync(0xffffffffu, a.x != 0.0f);
            unsigned m1 = __ballot_sync(0xffffffffu, a.y != 0.0f);
            unsigned m2 = __ballot_sync(0xffffffffu, a.z != 0.0f);
            unsigned m3 = __ballot_sync(0xffffffffu, a.w != 0.0f);
            int pre = cnt + __popc(m0 & lm) + __popc(m1 & lm)
                          + __popc(m2 & lm) + __popc(m3 & lm);
            int j0 = (base + lane) * 4;
            if (a.x != 0.0f) dst[pre] = j0;
            int o1 = pre + ((m0 >> lane) & 1);
            if (a.y != 0.0f) dst[o1] = j0 + 1;
            int o2 = o1 + ((m1 >> lane) & 1);
            if (a.z != 0.0f) dst[o2] = j0 + 2;
            int o3 = o2 + ((m2 >> lane) & 1);
            if (a.w != 0.0f) dst[o3] = j0 + 3;
            cnt += __popc(m0) + __popc(m1) + __popc(m2) + __popc(m3);
        }
        if (lane == 0) g_deg[n] = min(cnt, MAXDEG);
    } else if (bx < 800) {
        // ---------- Wc[k*S+s][d] = w_k * U[k][d][s] ----------
        float m = fmaxf(fmaxf(hw[0], hw[1]), fmaxf(hw[2], hw[3]));
        float e0 = expf(hw[0] - m), e1 = expf(hw[1] - m);
        float e2 = expf(hw[2] - m), e3 = expf(hw[3] - m);
        float sum = e0 + e1 + e2 + e3;
        int base = ((bx - 768) * 256 + tid) * 4;
        float4 u4 = *(const float4*)&U[base];
        int k = base / (D * S);
        int rem = base % (D * S);
        int d = rem / S;
        int s = rem % S;
        float wk = (k == 0 ? e0 : k == 1 ? e1 : k == 2 ? e2 : e3) / sum;
        g_Wc[(k * S + s + 0) * D + d] = wk * u4.x;
        g_Wc[(k * S + s + 1) * D + d] = wk * u4.y;
        g_Wc[(k * S + s + 2) * D + d] = wk * u4.z;
        g_Wc[(k * S + s + 3) * D + d] = wk * u4.w;
    } else {
        // ---------- orth pair (s,t) dots; 4 t per thread ----------
        const int kk[10] = {0, 0, 0, 0, 1, 1, 1, 2, 2, 3};
        const int ll[10] = {0, 1, 2, 3, 1, 2, 3, 2, 3, 3};
        int p = bx - 800;
        int k = kk[p], l = ll[p];
        int s = tid >> 3;
        int t0 = (tid & 7) * 4;
        float* uk = sm;
        float* ul = sm + 2048;
        float* red = sm + 4096;
        float c0 = 0.f, c1 = 0.f, c2 = 0.f, c3 = 0.f;
        for (int dc = 0; dc < D; dc += 64) {
            for (int i = tid; i < 2048; i += 256) {
                uk[i] = U[((size_t)k * D + dc) * S + i];
                ul[i] = U[((size_t)l * D + dc) * S + i];
            }
            __syncthreads();
#pragma unroll 8
            for (int d = 0; d < 64; d++) {
                float a = uk[d * 32 + s];
                float4 b = *(const float4*)&ul[d * 32 + t0];
                c0 += a * b.x; c1 += a * b.y; c2 += a * b.z; c3 += a * b.w;
            }
            __syncthreads();
        }
        if (k == l) {
            if (s == t0 + 0) c0 -= 1.0f;
            if (s == t0 + 1) c1 -= 1.0f;
            if (s == t0 + 2) c2 -= 1.0f;
            if (s == t0 + 3) c3 -= 1.0f;
        }
        red[tid] = (c0 * c0 + c1 * c1) + (c2 * c2 + c3 * c3);
        __syncthreads();
        for (int off = 128; off > 0; off >>= 1) {
            if (tid < off) red[tid] += red[tid + off];
            __syncthreads();
        }
        if (tid == 0) g_orth[p] = red[0];
    }
}

// ================= gram partials + last-block-per-k inversion =================
__global__ void __launch_bounds__(1024) k_gram(void) {
    __shared__ float sm[4224];
    int tid = threadIdx.x;
    int k = blockIdx.x >> 5;
    int chunk = blockIdx.x & 31;
    float* zs = sm;
    const float4* Z4 = (const float4*)(g_Zt + ((size_t)k * N + chunk * 128) * S);
    ((float4*)zs)[tid] = Z4[tid];
    __syncthreads();
    int s = tid >> 5, t = tid & 31;
    float g0 = 0.f, g1 = 0.f, g2 = 0.f, g3 = 0.f;
#pragma unroll 8
    for (int n = 0; n < 128; n += 4) {
        g0 += zs[(n + 0) * 32 + s] * zs[(n + 0) * 32 + t];
        g1 += zs[(n + 1) * 32 + s] * zs[(n + 1) * 32 + t];
        g2 += zs[(n + 2) * 32 + s] * zs[(n + 2) * 32 + t];
        g3 += zs[(n + 3) * 32 + s] * zs[(n + 3) * 32 + t];
    }
    g_gramP[(((size_t)k * 32 + chunk) * S + s) * S + t] = (g0 + g1) + (g2 + g3);
    __threadfence();
    __shared__ int isLast;
    if (tid == 0) {
        int v = atomicAdd(&g_ctrK[k], 1);
        isLast = (v == 31);
        if (v == 31) atomicExch(&g_ctrK[k], 0);
    }
    __syncthreads();
    if (!isLast) return;
    __threadfence();
    float g = 0.f;
    for (int c = 0; c < 32; c++)
        g += g_gramP[(((size_t)k * 32 + c) * S + s) * S + t];
    float (*aug)[66] = (float(*)[66])sm;
    __syncthreads();
    aug[s][t] = (s == t ? 1.0f : 0.0f) + COEFF * g;
    aug[s][32 + t] = (s == t ? 1.0f : 0.0f);
    __syncthreads();
    int r0 = tid >> 6, c0 = tid & 63;
    int tid2 = tid + 1024;
    int r1 = tid2 >> 6, c1 = tid2 & 63;
    for (int p = 0; p < 32; p++) {
        float inv = 1.0f / aug[p][p];
        float f0 = aug[r0][p], pr0 = aug[p][c0];
        float f1 = aug[r1][p], pr1 = aug[p][c1];
        __syncthreads();
        if (r0 == p) aug[p][c0] = pr0 * inv;
        else         aug[r0][c0] -= f0 * inv * pr0;
        if (r1 == p) aug[p][c1] = pr1 * inv;
        else         aug[r1][c1] -= f1 * inv * pr1;
        __syncthreads();
    }
    g_Minv[k * S * S + s * S + t] = aug[s][32 + t];
}

// ================= sparse attention on Z directly: q = Minv @ z_n, O = Minv @ acc =================
// Uses Minv symmetry: z_n^T Minv z_j = (Minv z_n)^T z_j.
// Minv[k] staged in smem stride-33 (all 8 warps per block share k).
__global__ void __launch_bounds__(256) k_attn(void) {
    __shared__ float Msh[32 * 33];
    __shared__ float sh[8][32];
    int w = threadIdx.x >> 5;
    int lane = threadIdx.x & 31;
    int gwarp = blockIdx.x * 8 + w;
    int k = gwarp >> 12;
    int n = gwarp & (N - 1);
    const float* __restrict__ Zt = g_Zt + (size_t)k * N * S;
    const int* __restrict__ cols = g_col + (size_t)n * MAXDEG;
    int dn = g_deg[n];
    int f2 = lane & 3;
    int rr = lane >> 2;
    const float LOG2E = 1.4426950408889634f;

    // stage Minv[k] (same k for all warps in block): 1024 floats
    {
        int tid = threadIdx.x;
        float4 v = ((const float4*)(g_Minv + k * S * S))[tid];
        int r = (tid * 4) >> 5;
        int c = (tid * 4) & 31;
        float* dst = &Msh[r * 33 + c];
        dst[0] = v.x; dst[1] = v.y; dst[2] = v.z; dst[3] = v.w;
    }
    __syncthreads();

    // prologue: y = Minv @ z_n (lane = component), then scale by log2 e
    sh[w][lane] = Zt[(size_t)n * S + lane];
    __syncwarp();
    {
        const float* Mr = &Msh[lane * 33];
        const float* zr = sh[w];
        float y = 0.f;
#pragma unroll
        for (int t = 0; t < 32; t += 4) {
            y += Mr[t] * zr[t] + Mr[t + 1] * zr[t + 1]
               + Mr[t + 2] * zr[t + 2] + Mr[t + 3] * zr[t + 3];
        }
        __syncwarp();
        sh[w][lane] = y * LOG2E;
    }
    __syncwarp();
    float4 qa = *(const float4*)&sh[w][f2 * 8];
    float4 qb = *(const float4*)&sh[w][f2 * 8 + 4];
    __syncwarp();

    float4 aa = make_float4(0.f, 0.f, 0.f, 0.f);
    float4 ab = make_float4(0.f, 0.f, 0.f, 0.f);
    float l = 0.f;

    int j0 = (rr < dn) ? cols[rr] : 0;
    int j1 = (8 + rr < dn) ? cols[8 + rr] : 0;

    for (int c0 = 0; c0 < dn; c0 += 16) {
        const float* vp0 = &Zt[(size_t)j0 * S + f2 * 8];
        const float* vp1 = &Zt[(size_t)j1 * S + f2 * 8];
        float4 va0 = *(const float4*)&vp0[0];
        float4 vb0 = *(const float4*)&vp0[4];
        float4 va1 = *(const float4*)&vp1[0];
        float4 vb1 = *(const float4*)&vp1[4];
        int nr0 = c0 + 16 + rr, nr1 = c0 + 24 + rr;
        int jn0 = (nr0 < dn) ? cols[nr0] : 0;
        int jn1 = (nr1 < dn) ? cols[nr1] : 0;

        bool in0 = (c0 + rr < dn);
        bool in1 = (c0 + 8 + rr < dn);

        float p0 = qa.x * va0.x + qa.y * va0.y + qa.z * va0.z + qa.w * va0.w
                 + qb.x * vb0.x + qb.y * vb0.y + qb.z * vb0.z + qb.w * vb0.w;
        float p1 = qa.x * va1.x + qa.y * va1.y + qa.z * va1.z + qa.w * va1.w
                 + qb.x * vb1.x + qb.y * vb1.y + qb.z * vb1.z + qb.w * vb1.w;
        p0 += __shfl_xor_sync(0xffffffffu, p0, 1);
        p1 += __shfl_xor_sync(0xffffffffu, p1, 1);
        p0 += __shfl_xor_sync(0xffffffffu, p0, 2);
        p1 += __shfl_xor_sync(0xffffffffu, p1, 2);
        p0 = in0 ? p0 : -1e30f;
        p1 = in1 ? p1 : -1e30f;
        float e0 = ex2fast(p0);
        float e1 = ex2fast(p1);
        l += e0 + e1;
        aa.x += e0 * va0.x; aa.y += e0 * va0.y; aa.z += e0 * va0.z; aa.w += e0 * va0.w;
        ab.x += e0 * vb0.x; ab.y += e0 * vb0.y; ab.z += e0 * vb0.z; ab.w += e0 * vb0.w;
        aa.x += e1 * va1.x; aa.y += e1 * va1.y; aa.z += e1 * va1.z; aa.w += e1 * va1.w;
        ab.x += e1 * vb1.x; ab.y += e1 * vb1.y; ab.z += e1 * vb1.z; ab.w += e1 * vb1.w;

        j0 = jn0; j1 = jn1;
    }

#pragma unroll
    for (int off = 4; off <= 16; off <<= 1) {
        aa.x += __shfl_xor_sync(0xffffffffu, aa.x, off);
        aa.y += __shfl_xor_sync(0xffffffffu, aa.y, off);
        aa.z += __shfl_xor_sync(0xffffffffu, aa.z, off);
        aa.w += __shfl_xor_sync(0xffffffffu, aa.w, off);
        ab.x += __shfl_xor_sync(0xffffffffu, ab.x, off);
        ab.y += __shfl_xor_sync(0xffffffffu, ab.y, off);
        ab.z += __shfl_xor_sync(0xffffffffu, ab.z, off);
        ab.w += __shfl_xor_sync(0xffffffffu, ab.w, off);
        l    += __shfl_xor_sync(0xffffffffu, l, off);
    }

    // epilogue: O = Minv @ acc / l   (acc staged to smem, then matvec; l on all lanes)
    if (rr == 0) {
        *(float4*)&sh[w][f2 * 8] = aa;
        *(float4*)&sh[w][f2 * 8 + 4] = ab;
    }
    __syncwarp();
    {
        const float* Mr = &Msh[lane * 33];
        const float* ar = sh[w];
        float o = 0.f;
#pragma unroll
        for (int t = 0; t < 32; t += 4) {
            o += Mr[t] * ar[t] + Mr[t + 1] * ar[t + 1]
               + Mr[t + 2] * ar[t + 2] + Mr[t + 3] * ar[t + 3];
        }
        g_O[(size_t)n * (K * S) + k * S + lane] = o / l;
    }
}

// ================= O2 = (I - lam*L) @ O_cat : 8-wide MLP gather =================
__global__ void k_lapO(const float* __restrict__ lambda_lap) {
    int n = blockIdx.x * 8 + (threadIdx.x >> 5);
    int lane = threadIdx.x & 31;
    const float4* O = (const float4*)g_O;
    const int* cols = g_col + (size_t)n * MAXDEG;
    int dn = g_deg[n];
    float4 o = O[(size_t)n * 32 + lane];
    float4 s = make_float4(0.f, 0.f, 0.f, 0.f);
    int c = 0;
    for (; c + 8 <= dn; c += 8) {
        float4 v0 = O[(size_t)cols[c] * 32 + lane];
        float4 v1 = O[(size_t)cols[c + 1] * 32 + lane];
        float4 v2 = O[(size_t)cols[c + 2] * 32 + lane];
        float4 v3 = O[(size_t)cols[c + 3] * 32 + lane];
        float4 v4 = O[(size_t)cols[c + 4] * 32 + lane];
        float4 v5 = O[(size_t)cols[c + 5] * 32 + lane];
        float4 v6 = O[(size_t)cols[c + 6] * 32 + lane];
        float4 v7 = O[(size_t)cols[c + 7] * 32 + lane];
        s.x += ((v0.x + v1.x) + (v2.x + v3.x)) + ((v4.x + v5.x) + (v6.x + v7.x));
        s.y += ((v0.y + v1.y) + (v2.y + v3.y)) + ((v4.y + v5.y) + (v6.y + v7.y));
        s.z += ((v0.z + v1.z) + (v2.z + v3.z)) + ((v4.z + v5.z) + (v6.z + v7.z));
        s.w += ((v0.w + v1.w) + (v2.w + v3.w)) + ((v4.w + v5.w) + (v6.w + v7.w));
    }
    for (; c < dn; c++) {
        float4 v = O[(size_t)cols[c] * 32 + lane];
        s.x += v.x; s.y += v.y; s.z += v.z; s.w += v.w;
    }
    float lam = lambda_lap[0];
    float fd = (float)dn;
    float4 r;
    r.x = o.x - lam * (fd * o.x - s.x);
    r.y = o.y - lam * (fd * o.y - s.y);
    r.z = o.z - lam * (fd * o.z - s.z);
    r.w = o.w - lam * (fd * o.w - s.w);
    ((float4*)g_O2)[(size_t)n * 32 + lane] = r;
}

// ================= H_out = softthresh(hops0 + ETA * O2 @ Wc) =================
__global__ void k_HoutG(const float* __restrict__ hops,
                        const float* __restrict__ threshold,
                        float* __restrict__ out) {
    __shared__ float as[32][33];
    __shared__ float ws[32][33];
    int n0 = blockIdx.x * 32, d0 = blockIdx.y * 32;
    int lane = threadIdx.x & 31;
    int row = threadIdx.x >> 5;
    float acc[4] = {0.f, 0.f, 0.f, 0.f};
    for (int cc = 0; cc < K * S; cc += 32) {
#pragma unroll
        for (int i = 0; i < 4; i++) {
            int r = row + i * 8;
            as[r][lane] = g_O2[(size_t)(n0 + r) * (K * S) + cc + lane];
            ws[r][lane] = g_Wc[(size_t)(cc + r) * D + d0 + lane];
        }
        __syncthreads();
#pragma unroll
        for (int dd = 0; dd < 32; dd++) {
            float wv = ws[dd][lane];
#pragma unroll
            for (int i = 0; i < 4; i++) acc[i] += as[row * 4 + i][dd] * wv;
        }
        __syncthreads();
    }
    float th = threshold[d0 + lane];
#pragma unroll
    for (int i = 0; i < 4; i++) {
        int n = n0 + row * 4 + i;
        float hh = hops[(size_t)n * D + d0 + lane] + ETA * acc[i];
        float ab = fabsf(hh) - th;
        out[(size_t)n * D + d0 + lane] = (ab > 0.f) ? copysignf(ab, hh) : 0.f;
    }
}

// ================= lap_smooth partials (symmetric half, 8-wide MLP) + fused final =================
__global__ void k_lapF(const float* __restrict__ Hout, const float* __restrict__ hw,
                       float* __restrict__ out, int out_size) {
    __shared__ int hd[4];
    if (threadIdx.x < 4) {
        int nn = blockIdx.x * 4 + threadIdx.x;
        const int* cc = g_col + (size_t)nn * MAXDEG;
        int lo = 0, hi = g_deg[nn];
        while (lo < hi) {
            int mid = (lo + hi) >> 1;
            if (cc[mid] < nn) lo = mid + 1; else hi = mid;
        }
        hd[threadIdx.x] = lo;
    }
    __syncthreads();
    int g = threadIdx.x >> 6;
    int n = blockIdx.x * 4 + g;
    int t = threadIdx.x & 63;
    const float4* H = (const float4*)Hout;
    const int* cols = g_col + (size_t)n * MAXDEG;
    int dn = g_deg[n];
    int hn = hd[g];
    float4 h = H[(size_t)n * 64 + t];
    float4 vs = make_float4(0.f, 0.f, 0.f, 0.f);
    int c = 0;
    for (; c + 8 <= hn; c += 8) {
        float4 v0 = H[(size_t)cols[c] * 64 + t];
        float4 v1 = H[(size_t)cols[c + 1] * 64 + t];
        float4 v2 = H[(size_t)cols[c + 2] * 64 + t];
        float4 v3 = H[(size_t)cols[c + 3] * 64 + t];
        float4 v4 = H[(size_t)cols[c + 4] * 64 + t];
        float4 v5 = H[(size_t)cols[c + 5] * 64 + t];
        float4 v6 = H[(size_t)cols[c + 6] * 64 + t];
        float4 v7 = H[(size_t)cols[c + 7] * 64 + t];
        vs.x += ((v0.x + v1.x) + (v2.x + v3.x)) + ((v4.x + v5.x) + (v6.x + v7.x));
        vs.y += ((v0.y + v1.y) + (v2.y + v3.y)) + ((v4.y + v5.y) + (v6.y + v7.y));
        vs.z += ((v0.z + v1.z) + (v2.z + v3.z)) + ((v4.z + v5.z) + (v6.z + v7.z));
        vs.w += ((v0.w + v1.w) + (v2.w + v3.w)) + ((v4.w + v5.w) + (v6.w + v7.w));
    }
    for (; c < hn; c++) {
        float4 v = H[(size_t)cols[c] * 64 + t];
        vs.x += v.x; vs.y += v.y; vs.z += v.z; vs.w += v.w;
    }
    float fd = (float)dn - 1.0f;
    float dot = fd * (h.x * h.x + h.y * h.y + h.z * h.z + h.w * h.w)
              - 2.0f * (h.x * vs.x + h.y * vs.y + h.z * vs.z + h.w * vs.w);
    dot = warpSum(dot);
    __shared__ float sred[8];
    if ((threadIdx.x & 31) == 0) sred[threadIdx.x >> 5] = dot;
    __syncthreads();
    if (threadIdx.x < 4)
        g_partials[blockIdx.x * 4 + threadIdx.x] =
            sred[threadIdx.x * 2] + sred[threadIdx.x * 2 + 1];

    __threadfence();
    __shared__ int isLast;
    if (threadIdx.x == 0) {
        int v = atomicAdd(&g_ctr, 1);
        isLast = (v == (int)gridDim.x - 1) ? 1 : 0;
        if (isLast) atomicExch(&g_ctr, 0);
    }
    __syncthreads();
    if (!isLast) return;
    __threadfence();

    float v = 0.f;
    for (int i = threadIdx.x; i < N; i += 256) v += g_partials[i];
    __shared__ float red2[256];
    red2[threadIdx.x] = v;
    __syncthreads();
    for (int off = 128; off > 0; off >>= 1) {
        if (threadIdx.x < off) red2[threadIdx.x] += red2[threadIdx.x + off];
        __syncthreads();
    }
    if (threadIdx.x == 0) {
        float orth = 0.f;
        for (int p = 0; p < 10; p++) orth += g_orth[p];
        float m = fmaxf(fmaxf(hw[0], hw[1]), fmaxf(hw[2], hw[3]));
        float e0 = expf(hw[0] - m), e1 = expf(hw[1] - m);
        float e2 = expf(hw[2] - m), e3 = expf(hw[3] - m);
        float s = e0 + e1 + e2 + e3;
        int base = N * D;
        if (base < out_size) out[base] = orth;
        if (base + 1 < out_size) out[base + 1] = red2[0];
        if (base + 2 < out_size) out[base + 2] = e0 / s;
        if (base + 3 < out_size) out[base + 3] = e1 / s;
        if (base + 4 < out_size) out[base + 4] = e2 / s;
        if (base + 5 < out_size) out[base + 5] = e3 / s;
    }
}

// ---------------- launch ----------------
extern "C" void kernel_launch(void* const* d_in, const int* in_sizes, int n_in,
                              void* d_out, int out_size) {
    const float* hops      = (const float*)d_in[0];
    const float* adj       = (const float*)d_in[1];
    const float* U         = (const float*)d_in[3];
    const float* hw        = (const float*)d_in[4];
    const float* threshold = (const float*)d_in[5];
    const float* lam       = (const float*)d_in[6];
    float* out = (float*)d_out;

    k_mega1<<<810, 256>>>(hops, adj, U, hw);
    k_gram<<<128, 1024>>>();
    k_attn<<<(K * N) / 8, 256>>>();
    k_lapO<<<N / 8, 256>>>(lam);
    {
        dim3 g(N / 32, D / 32);
        k_HoutG<<<g, 256>>>(hops, threshold, out);
    }
    k_lapF<<<N / 4, 256>>>(out, hw, out, out_size);
}